// round 9
// baseline (speedup 1.0000x reference)
#include <cuda_runtime.h>
#include <cuda_bf16.h>

#define BB 64
#define NN 128
#define FF 4
#define HH 100
#define HHP 104          // padded row (104*4 = 416 bytes, 16B-aligned rows)
#define NQ 25            // HH/4 d-quads
#define PP 8128          // NN*(NN-1)/2
#define NODE_ITEMS (BB*NQ*NN)        // 204800
#define NODE_BLOCKS 128
#define ITEMS_PER_BLOCK (NODE_ITEMS/NODE_BLOCKS)  // 1600

typedef unsigned long long u64;

// Scratch (device globals: allocation-free)
__device__ __align__(16) float g_A2[BB*NN*HHP];     // [b][n][d]  (c2 folded in)
__device__ __align__(16) float g_B2q[BB*NQ*NN*4];   // [b][dq][n][4]

// ---- packed f32x2 helpers (PTX-only instructions on sm_103a) ----
__device__ __forceinline__ u64 addx2(u64 a, u64 b) {
    u64 r; asm("add.rn.f32x2 %0, %1, %2;" : "=l"(r) : "l"(a), "l"(b)); return r;
}
__device__ __forceinline__ u64 fmax2z(u64 t) {   // relu on both halves
    union { u64 u; float2 f; } v; v.u = t;
    v.f.x = fmaxf(v.f.x, 0.f);
    v.f.y = fmaxf(v.f.y, 0.f);
    return v.u;
}
__device__ __forceinline__ u64 fmafx2(u64 a, u64 b, u64 c) {
    u64 r; asm("fma.rn.f32x2 %0, %1, %2, %3;" : "=l"(r) : "l"(a), "l"(b), "l"(c)); return r;
}

// ---------------------------------------------------------------- K1: fused fold + node transform
// Each block redundantly folds W1@W2 (+biases) into smem (80 KFLOP — trivial),
// then transforms its slice of nodes. No separate weight kernel, no launch gap.
__global__ void __launch_bounds__(256) k_nodes(const float* __restrict__ x,
                                               const float* __restrict__ W1,
                                               const float* __restrict__ b1,
                                               const float* __restrict__ W2,
                                               const float* __restrict__ b2) {
    __shared__ float sW1[2*FF][HH];
    __shared__ float sb1[HH];
    __shared__ __align__(16) float sM1[FF][HHP];
    __shared__ __align__(16) float sM2[FF][HHP];
    __shared__ __align__(16) float sc2[HHP];
    int tid = threadIdx.x;

    for (int i = tid; i < 2*FF*HH; i += 256) sW1[i / HH][i % HH] = W1[i];
    for (int i = tid; i < HH; i += 256)      sb1[i] = b1[i];
    __syncthreads();

    if (tid < HH) {
        int d = tid;
        float m1[FF] = {0.f,0.f,0.f,0.f};
        float m2[FF] = {0.f,0.f,0.f,0.f};
        float c = 0.f;
        #pragma unroll 4
        for (int k = 0; k < HH; ++k) {
            float w = W2[k * HH + d];           // coalesced across d
            #pragma unroll
            for (int f = 0; f < FF; ++f) {
                m1[f] = fmaf(sW1[f][k],      w, m1[f]);
                m2[f] = fmaf(sW1[FF + f][k], w, m2[f]);
            }
            c = fmaf(sb1[k], w, c);
        }
        #pragma unroll
        for (int f = 0; f < FF; ++f) { sM1[f][d] = m1[f]; sM2[f][d] = m2[f]; }
        sc2[d] = c + b2[d];
    }
    __syncthreads();

    int base = blockIdx.x * ITEMS_PER_BLOCK;
    for (int it = tid; it < ITEMS_PER_BLOCK; it += 256) {
        int t  = base + it;
        int n  = t & (NN - 1);
        int dq = (t / NN) % NQ;
        int b  = t / (NN * NQ);
        int d0 = dq * 4;

        float4 xv = *(const float4*)(x + (b * NN + n) * FF);
        float4 a  = *(const float4*)(&sc2[d0]);
        float4 v  = make_float4(0.f, 0.f, 0.f, 0.f);
        #pragma unroll
        for (int f = 0; f < FF; ++f) {
            float xf = (f == 0) ? xv.x : (f == 1) ? xv.y : (f == 2) ? xv.z : xv.w;
            float4 m1 = *(const float4*)(&sM1[f][d0]);
            float4 m2 = *(const float4*)(&sM2[f][d0]);
            a.x = fmaf(xf, m1.x, a.x); a.y = fmaf(xf, m1.y, a.y);
            a.z = fmaf(xf, m1.z, a.z); a.w = fmaf(xf, m1.w, a.w);
            v.x = fmaf(xf, m2.x, v.x); v.y = fmaf(xf, m2.y, v.y);
            v.z = fmaf(xf, m2.z, v.z); v.w = fmaf(xf, m2.w, v.w);
        }
        *(float4*)(g_A2 + (b * NN + n) * HHP + d0) = a;
        *(float4*)(g_B2q + ((b * NQ + dq) * NN + n) * 4) = v;
    }
}

// ---------------------------------------------------------------- K2: pair kernel
// Warp-per-tile: 4 i1-rows x 32 i2-lanes; 80 tiles per batch.
// Inner math in packed f32x2 (FADD2/FFMA2 on fma pipe, FMNMX relu on alu pipe).
__global__ void __launch_bounds__(128) k_pairs(const float* __restrict__ W3,
                                               const float* __restrict__ b3p,
                                               float* __restrict__ out) {
    int warp_gid = (blockIdx.x * blockDim.x + threadIdx.x) >> 5;
    int lane = threadIdx.x & 31;

    int b   = warp_gid / 80;
    int tix = warp_gid % 80;
    int j, I0;
    if (tix < 8)       { j = 0; I0 = tix * 4; }
    else if (tix < 24) { j = 1; I0 = (tix - 8) * 4; }
    else if (tix < 48) { j = 2; I0 = (tix - 24) * 4; }
    else               { j = 3; I0 = (tix - 48) * 4; }
    int J0 = j * 32;
    int i2 = J0 + lane;

    const float* A2 = g_A2 + (b * NN + I0) * HHP;                        // 4 rows, c2 folded
    const ulonglong2* B2 = (const ulonglong2*)(g_B2q + (b * NQ * NN + i2) * 4);
    u64 accA[4] = {0ull, 0ull, 0ull, 0ull};   // packed (d even-pair) accumulators
    u64 accB[4] = {0ull, 0ull, 0ull, 0ull};
    float b3 = b3p[0];

    #pragma unroll 5
    for (int q = 0; q < NQ; ++q) {
        int d0 = q * 4;
        ulonglong2 a0 = *(const ulonglong2*)(A2 + 0 * HHP + d0);
        ulonglong2 a1 = *(const ulonglong2*)(A2 + 1 * HHP + d0);
        ulonglong2 a2 = *(const ulonglong2*)(A2 + 2 * HHP + d0);
        ulonglong2 a3 = *(const ulonglong2*)(A2 + 3 * HHP + d0);
        ulonglong2 wq = *(const ulonglong2*)(W3 + d0);
        ulonglong2 bq = B2[q * NN];

        accA[0] = fmafx2(fmax2z(addx2(a0.x, bq.x)), wq.x, accA[0]);
        accA[1] = fmafx2(fmax2z(addx2(a1.x, bq.x)), wq.x, accA[1]);
        accA[2] = fmafx2(fmax2z(addx2(a2.x, bq.x)), wq.x, accA[2]);
        accA[3] = fmafx2(fmax2z(addx2(a3.x, bq.x)), wq.x, accA[3]);

        accB[0] = fmafx2(fmax2z(addx2(a0.y, bq.y)), wq.y, accB[0]);
        accB[1] = fmafx2(fmax2z(addx2(a1.y, bq.y)), wq.y, accB[1]);
        accB[2] = fmafx2(fmax2z(addx2(a2.y, bq.y)), wq.y, accB[2]);
        accB[3] = fmafx2(fmax2z(addx2(a3.y, bq.y)), wq.y, accB[3]);
    }

    #pragma unroll
    for (int t = 0; t < 4; ++t) {
        int i1 = I0 + t;
        if (i1 < i2) {
            union { u64 u; float2 f; } ua, ub;
            ua.u = accA[t]; ub.u = accB[t];
            float z = (ua.f.x + ua.f.y) + (ub.f.x + ub.f.y) + b3;
            float s = 1.f / (1.f + __expf(-z));
            int p = i1 * (2 * NN - 1 - i1) / 2 + (i2 - i1 - 1);
            out[b * PP + p] = s;
        }
    }
}

// ---------------------------------------------------------------- launch
extern "C" void kernel_launch(void* const* d_in, const int* in_sizes, int n_in,
                              void* d_out, int out_size) {
    const float* x  = (const float*)d_in[0];
    // d_in[1] = in_hitnr (unused by reference)
    const float* W1 = (const float*)d_in[2];
    const float* b1 = (const float*)d_in[3];
    const float* W2 = (const float*)d_in[4];
    const float* b2 = (const float*)d_in[5];
    const float* W3 = (const float*)d_in[6];
    const float* b3 = (const float*)d_in[7];
    float* out = (float*)d_out;

    k_nodes<<<NODE_BLOCKS, 256>>>(x, W1, b1, W2, b2);

    // 64 batches * 80 tiles = 5120 warps; 4 warps per 128-thread block
    k_pairs<<<5120 / 4, 128>>>(W3, b3, out);
}